// round 3
// baseline (speedup 1.0000x reference)
#include <cuda_runtime.h>

// QCNN closed form (see R0): each layer k maps x_w <- prod_{j<=w} cos(x_j + theta_k_j),
// then out = sigmoid(x @ W + b).
//
// R2 change: latency-bound at 1.7 warps/SMSP with one serial chain each.
// Process 2 batch elements per thread (2x ILP on the MUFU/FMUL critical path),
// load inputs as 5 aligned float4s (80B contiguous per thread), stage the 104
// parameter floats in shared memory, and use 64-thread blocks x 256 so all
// 148 SMs are covered.

#define NW 10
#define NLAYERS 6

__global__ __launch_bounds__(64) void qcnn_kernel(
    const float* __restrict__ inputs,   // (B, 10)
    const float* __restrict__ thetas,   // (6, 10)
    const float* __restrict__ W,        // (10, 4)
    const float* __restrict__ bias,     // (4,)
    float* __restrict__ out,            // (B, 4)
    int nThreads)                       // B / 2
{
    __shared__ float s_th[NLAYERS * NW];  // 60
    __shared__ float s_w[NW * 4];         // 40
    __shared__ float s_b[4];

    // Stage parameters (uniform, tiny).
    for (int i = threadIdx.x; i < NLAYERS * NW; i += blockDim.x) s_th[i] = thetas[i];
    for (int i = threadIdx.x; i < NW * 4; i += blockDim.x)       s_w[i] = W[i];
    if (threadIdx.x < 4) s_b[threadIdx.x] = bias[threadIdx.x];
    __syncthreads();

    int t = blockIdx.x * blockDim.x + threadIdx.x;
    if (t >= nThreads) return;

    // Two batch elements: 2t and 2t+1 -> 20 contiguous floats = 5 aligned float4s.
    float xa[NW], xb[NW];
    {
        const float4* p = reinterpret_cast<const float4*>(inputs) + (size_t)t * 5;
        float4 v0 = p[0], v1 = p[1], v2 = p[2], v3 = p[3], v4 = p[4];
        xa[0] = v0.x; xa[1] = v0.y; xa[2] = v0.z; xa[3] = v0.w;
        xa[4] = v1.x; xa[5] = v1.y; xa[6] = v1.z; xa[7] = v1.w;
        xa[8] = v2.x; xa[9] = v2.y;
        xb[0] = v2.z; xb[1] = v2.w;
        xb[2] = v3.x; xb[3] = v3.y; xb[4] = v3.z; xb[5] = v3.w;
        xb[6] = v4.x; xb[7] = v4.y; xb[8] = v4.z; xb[9] = v4.w;
    }

    // 6 layers of prefix-product-of-cosines, two independent chains (ILP=2).
    #pragma unroll
    for (int k = 0; k < NLAYERS; k++) {
        float pa = 1.0f, pb = 1.0f;
        #pragma unroll
        for (int w = 0; w < NW; w++) {
            float th = s_th[k * NW + w];
            float ca = __cosf(xa[w] + th);
            float cb = __cosf(xb[w] + th);
            pa *= ca; xa[w] = pa;
            pb *= cb; xb[w] = pb;
        }
    }

    // Linear layer + sigmoid for both elements.
    float aa[4], ab[4];
    #pragma unroll
    for (int o = 0; o < 4; o++) { aa[o] = s_b[o]; ab[o] = s_b[o]; }
    #pragma unroll
    for (int w = 0; w < NW; w++) {
        #pragma unroll
        for (int o = 0; o < 4; o++) {
            float wv = s_w[w * 4 + o];
            aa[o] = fmaf(xa[w], wv, aa[o]);
            ab[o] = fmaf(xb[w], wv, ab[o]);
        }
    }

    float4 ra, rb;
    ra.x = __frcp_rn(1.0f + __expf(-aa[0]));
    ra.y = __frcp_rn(1.0f + __expf(-aa[1]));
    ra.z = __frcp_rn(1.0f + __expf(-aa[2]));
    ra.w = __frcp_rn(1.0f + __expf(-aa[3]));
    rb.x = __frcp_rn(1.0f + __expf(-ab[0]));
    rb.y = __frcp_rn(1.0f + __expf(-ab[1]));
    rb.z = __frcp_rn(1.0f + __expf(-ab[2]));
    rb.w = __frcp_rn(1.0f + __expf(-ab[3]));

    float4* po = reinterpret_cast<float4*>(out) + (size_t)t * 2;
    po[0] = ra;
    po[1] = rb;
}

extern "C" void kernel_launch(void* const* d_in, const int* in_sizes, int n_in,
                              void* d_out, int out_size) {
    const float* inputs = (const float*)d_in[0];  // (B, 10)
    const float* thetas = (const float*)d_in[1];  // (6, 10)
    const float* W      = (const float*)d_in[2];  // (10, 4)
    const float* bias   = (const float*)d_in[3];  // (4,)
    float* out = (float*)d_out;

    int B = in_sizes[0] / NW;        // 32768
    int nThreads = B / 2;            // 16384
    int threads = 64;
    int blocks = (nThreads + threads - 1) / threads;  // 256
    qcnn_kernel<<<blocks, threads>>>(inputs, thetas, W, bias, out, nThreads);
}

// round 4
// speedup vs baseline: 1.0417x; 1.0417x over previous
#include <cuda_runtime.h>

// QCNN closed form (see R0): layer k maps x_w <- prod_{j<=w} cos(x_j + theta_k_j),
// then out = sigmoid(x @ W + b).
//
// R4: back to R2's winning occupancy shape (1 elem/thread, 1024 warps,
// block=128, no smem). New: Hillis-Steele prefix-product tree (chain depth
// 10 -> 4 FMULs per layer -- we are latency-bound, issue% ~13%, so trading
// +16 muls/layer for -24 cyc of dependency depth is right), and float2 input
// loads (rows are 40B -> 8B-aligned, 5 LDG.64 instead of 10 LDG.32).

#define NW 10
#define NLAYERS 6

__global__ __launch_bounds__(128) void qcnn_kernel(
    const float* __restrict__ inputs,   // (B, 10)
    const float* __restrict__ thetas,   // (6, 10)
    const float* __restrict__ W,        // (10, 4)
    const float* __restrict__ bias,     // (4,)
    float* __restrict__ out,            // (B, 4)
    int B)
{
    int b = blockIdx.x * blockDim.x + threadIdx.x;
    if (b >= B) return;

    // Row is 40 bytes, 8B-aligned for every b -> 5 vectorized float2 loads.
    float x[NW];
    {
        const float2* p = reinterpret_cast<const float2*>(inputs + (size_t)b * NW);
        float2 v0 = __ldg(p + 0), v1 = __ldg(p + 1), v2 = __ldg(p + 2),
               v3 = __ldg(p + 3), v4 = __ldg(p + 4);
        x[0] = v0.x; x[1] = v0.y; x[2] = v1.x; x[3] = v1.y;
        x[4] = v2.x; x[5] = v2.y; x[6] = v3.x; x[7] = v3.y;
        x[8] = v4.x; x[9] = v4.y;
    }

    // 6 layers: cos, then prefix product via Hillis-Steele tree (depth 4).
    #pragma unroll
    for (int k = 0; k < NLAYERS; k++) {
        float c[NW];
        #pragma unroll
        for (int w = 0; w < NW; w++)
            c[w] = __cosf(x[w] + __ldg(thetas + k * NW + w));

        // In-place inclusive prefix product, log-depth.
        // Descending order within a step reads not-yet-updated (old) values.
        #pragma unroll
        for (int w = NW - 1; w >= 1; w--) c[w] *= c[w - 1];   // span 2
        #pragma unroll
        for (int w = NW - 1; w >= 2; w--) c[w] *= c[w - 2];   // span 4
        #pragma unroll
        for (int w = NW - 1; w >= 4; w--) c[w] *= c[w - 4];   // span 8
        #pragma unroll
        for (int w = NW - 1; w >= 8; w--) c[w] *= c[w - 8];   // span 16 (full)

        #pragma unroll
        for (int w = 0; w < NW; w++) x[w] = c[w];
    }

    // Final linear layer + sigmoid. W is (10, 4) row-major.
    float acc[4];
    #pragma unroll
    for (int o = 0; o < 4; o++) acc[o] = __ldg(bias + o);
    #pragma unroll
    for (int w = 0; w < NW; w++) {
        float xv = x[w];
        #pragma unroll
        for (int o = 0; o < 4; o++) acc[o] = fmaf(xv, __ldg(W + w * 4 + o), acc[o]);
    }

    float4 r;
    r.x = __frcp_rn(1.0f + __expf(-acc[0]));
    r.y = __frcp_rn(1.0f + __expf(-acc[1]));
    r.z = __frcp_rn(1.0f + __expf(-acc[2]));
    r.w = __frcp_rn(1.0f + __expf(-acc[3]));
    reinterpret_cast<float4*>(out)[b] = r;
}

extern "C" void kernel_launch(void* const* d_in, const int* in_sizes, int n_in,
                              void* d_out, int out_size) {
    const float* inputs = (const float*)d_in[0];  // (B, 10)
    const float* thetas = (const float*)d_in[1];  // (6, 10)
    const float* W      = (const float*)d_in[2];  // (10, 4)
    const float* bias   = (const float*)d_in[3];  // (4,)
    float* out = (float*)d_out;

    int B = in_sizes[0] / NW;  // 32768
    int threads = 128;
    int blocks = (B + threads - 1) / threads;  // 256
    qcnn_kernel<<<blocks, threads>>>(inputs, thetas, W, bias, out, B);
}